// round 6
// baseline (speedup 1.0000x reference)
#include <cuda_runtime.h>
#include <cuda_bf16.h>
#include <cstdint>
#include <math.h>

#define T_TOK 2048
#define NE 8
#define DDIM 768
#define HDIM 3072
#define NSLOT (T_TOK * 2)

#define BM 128
#define BN 128
#define BK 16

// ---------------------------------------------------------------- mma helper
__device__ __forceinline__ void mma_bf16(float* c, const uint32_t* a,
                                         uint32_t b0, uint32_t b1) {
    asm volatile("mma.sync.aligned.m16n8k16.row.col.f32.bf16.bf16.f32 "
        "{%0,%1,%2,%3}, {%4,%5,%6,%7}, {%8,%9}, {%0,%1,%2,%3};"
        : "+f"(c[0]), "+f"(c[1]), "+f"(c[2]), "+f"(c[3])
        : "r"(a[0]), "r"(a[1]), "r"(a[2]), "r"(a[3]), "r"(b0), "r"(b1));
}

// ---------------------------------------------------------------- scratch
__device__ int g_ok;
// scalar-fallback buffers
__device__ float g_h[(size_t)NSLOT * HDIM];
__device__ float g_g[(size_t)NSLOT * HDIM];
// shared output buffer
__device__ float g_y[(size_t)NSLOT * DDIM];
// mma-path buffers
__device__ __align__(16) __nv_bfloat16 g_xhi[T_TOK * DDIM];
__device__ __align__(16) __nv_bfloat16 g_xlo[T_TOK * DDIM];
__device__ __align__(16) __nv_bfloat16 g_w1hi[(size_t)NE * HDIM * DDIM]; // [e][h][d]
__device__ __align__(16) __nv_bfloat16 g_w1lo[(size_t)NE * HDIM * DDIM];
__device__ __align__(16) __nv_bfloat16 g_w2hi[(size_t)NE * HDIM * DDIM];
__device__ __align__(16) __nv_bfloat16 g_w2lo[(size_t)NE * HDIM * DDIM];
__device__ __align__(16) __nv_bfloat16 g_wphi[(size_t)NE * DDIM * HDIM]; // [e][d][h]
__device__ __align__(16) __nv_bfloat16 g_wplo[(size_t)NE * DDIM * HDIM];
__device__ __align__(16) __nv_bfloat16 g_acthi[(size_t)NSLOT * HDIM];
__device__ __align__(16) __nv_bfloat16 g_actlo[(size_t)NSLOT * HDIM];
// routing
__device__ int   g_cnt[NE];
__device__ int   g_cnt2[NE];
__device__ int   g_off[NE];
__device__ float g_probs[NE];
__device__ int   g_slot_token[NSLOT];
__device__ int   g_tok_slot[NSLOT];
__device__ float g_tok_gate[NSLOT];
__device__ int   g_tok_exp[NSLOT];

__device__ __forceinline__ int flag_on()  { return *(volatile int*)&g_ok; }

// ---------------------------------------------------------------- gate path
__global__ void zero_stats() {
    int i = threadIdx.x;
    if (i < NE) { g_cnt[i] = 0; g_probs[i] = 0.f; }
    if (i == 0) g_ok = 1;
}

// probe: one warp runs one m16n8k16 on known data; clears g_ok on mismatch
__global__ void probe_kernel() {
    __shared__ __align__(16) __nv_bfloat16 sA[16][40];
    __shared__ __align__(16) __nv_bfloat16 sB[8][40];
    __shared__ int sbad;
    int lane = threadIdx.x;
    if (lane == 0) sbad = 0;
    for (int i = lane; i < 256; i += 32) {
        int m = i >> 4, k = i & 15;
        sA[m][k] = __float2bfloat16(0.03f * m - 0.07f * k + 0.11f);
    }
    for (int i = lane; i < 128; i += 32) {
        int n = i >> 4, k = i & 15;
        sB[n][k] = __float2bfloat16(0.05f * n + 0.02f * k - 0.3f);
    }
    __syncthreads();
    int qr = lane >> 2, qc = (lane & 3) * 2;
    uint32_t a[4], b0, b1;
    a[0] = *(const uint32_t*)&sA[qr][qc];
    a[1] = *(const uint32_t*)&sA[qr + 8][qc];
    a[2] = *(const uint32_t*)&sA[qr][qc + 8];
    a[3] = *(const uint32_t*)&sA[qr + 8][qc + 8];
    b0 = *(const uint32_t*)&sB[qr][qc];
    b1 = *(const uint32_t*)&sB[qr][qc + 8];
    float c[4] = {0.f, 0.f, 0.f, 0.f};
    mma_bf16(c, a, b0, b1);
#pragma unroll
    for (int i = 0; i < 4; i++) {
        int row = qr + (i >> 1) * 8;
        int col = (lane & 3) * 2 + (i & 1);
        float ref = 0.f;
        for (int k = 0; k < 16; k++) {
            float av = __bfloat162float(__float2bfloat16(0.03f * row - 0.07f * k + 0.11f));
            float bv = __bfloat162float(__float2bfloat16(0.05f * col + 0.02f * k - 0.3f));
            ref += av * bv;
        }
        if (fabsf(c[i] - ref) > 1e-2f) atomicExch(&sbad, 1);
    }
    __syncthreads();
    if (lane == 0 && sbad) g_ok = 0;
}

__global__ void gate_kernel(const float* __restrict__ x,
                            const float* __restrict__ noise,
                            const float* __restrict__ gw,
                            const float* __restrict__ nw,
                            float* __restrict__ out_ids)
{
    int t = blockIdx.x;
    int tid = threadIdx.x;
    const float* xr = x + (size_t)t * DDIM;

    float acc[NE];
#pragma unroll
    for (int e = 0; e < NE; e++) acc[e] = 0.f;
    for (int d = tid; d < DDIM; d += 128) {
        float xv = xr[d];
        const float* w = gw + d * NE;
#pragma unroll
        for (int e = 0; e < NE; e++) acc[e] += xv * w[e];
    }

    __shared__ float sm[NE][128];
#pragma unroll
    for (int e = 0; e < NE; e++) sm[e][tid] = acc[e];
    __syncthreads();
    for (int s = 64; s > 0; s >>= 1) {
        if (tid < s) {
#pragma unroll
            for (int e = 0; e < NE; e++) sm[e][tid] += sm[e][tid + s];
        }
        __syncthreads();
    }

    if (tid == 0) {
        float lg[NE], ns[NE];
#pragma unroll
        for (int e = 0; e < NE; e++) {
            lg[e] = sm[e][0];
            ns[e] = lg[e] + noise[t * NE + e] * nw[e];
        }
        int i0 = 0;
#pragma unroll
        for (int e = 1; e < NE; e++) if (ns[e] > ns[i0]) i0 = e;
        int i1 = (i0 == 0) ? 1 : 0;
#pragma unroll
        for (int e = 0; e < NE; e++) if (e != i0 && ns[e] > ns[i1]) i1 = e;

        float q  = expf(ns[i1] - ns[i0]);
        float p1 = q / (1.f + q);
        float p0 = 1.f - p1;

        g_tok_exp[t * 2 + 0] = i0;  g_tok_exp[t * 2 + 1] = i1;
        g_tok_gate[t * 2 + 0] = p0; g_tok_gate[t * 2 + 1] = p1;
        if (out_ids) {
            out_ids[t * 2 + 0] = (float)i0;
            out_ids[t * 2 + 1] = (float)i1;
        }
        atomicAdd(&g_cnt[i0], 1);
        atomicAdd(&g_cnt[i1], 1);

        float m = lg[0];
#pragma unroll
        for (int e = 1; e < NE; e++) m = fmaxf(m, lg[e]);
        float ex[NE], sum = 0.f;
#pragma unroll
        for (int e = 0; e < NE; e++) { ex[e] = expf(lg[e] - m); sum += ex[e]; }
        float inv = 1.f / sum;
#pragma unroll
        for (int e = 0; e < NE; e++) atomicAdd(&g_probs[e], ex[e] * inv);
    }
}

__global__ void finalize_kernel(float* __restrict__ out_lb) {
    if (threadIdx.x == 0 && blockIdx.x == 0) {
        int off = 0;
        for (int e = 0; e < NE; e++) { g_off[e] = off; off += g_cnt[e]; g_cnt2[e] = 0; }
        float accv = 0.f;
        for (int e = 0; e < NE; e++) {
            float d = g_probs[e] / (float)T_TOK - 1.0f / (float)NE;
            accv += d * d;
        }
        if (out_lb) out_lb[0] = accv / (float)NE * 0.01f;
    }
}

__global__ void scatter_kernel() {
    int t = blockIdx.x * blockDim.x + threadIdx.x;
    if (t >= T_TOK) return;
#pragma unroll
    for (int k2 = 0; k2 < 2; k2++) {
        int e = g_tok_exp[t * 2 + k2];
        int pos = atomicAdd(&g_cnt2[e], 1);
        int slot = g_off[e] + pos;
        g_slot_token[slot] = t;
        g_tok_slot[t * 2 + k2] = slot;
    }
}

// ---------------------------------------------------------------- converts (gated)
__global__ void convert_x_kernel(const float* __restrict__ x) {
    if (!flag_on()) return;
    size_t i = (size_t)blockIdx.x * blockDim.x + threadIdx.x;
    float4 v = ((const float4*)x)[i];
    float vv[4] = { v.x, v.y, v.z, v.w };
    __nv_bfloat16 hb[4], lb[4];
#pragma unroll
    for (int j = 0; j < 4; j++) {
        hb[j] = __float2bfloat16(vv[j]);
        lb[j] = __float2bfloat16(vv[j] - __bfloat162float(hb[j]));
    }
    uint64_t hv, lv;
    memcpy(&hv, hb, 8); memcpy(&lv, lb, 8);
    *(uint64_t*)(g_xhi + i * 4) = hv;
    *(uint64_t*)(g_xlo + i * 4) = lv;
}

// W [E][R][C] (C contiguous) -> Bhi/Blo [E][C][R]
__global__ void transpose_convert(const float* __restrict__ W,
                                  __nv_bfloat16* __restrict__ Bhi,
                                  __nv_bfloat16* __restrict__ Blo,
                                  int R, int C)
{
    if (!flag_on()) return;
    __shared__ float tile[32][33];
    int e = blockIdx.z;
    int c0 = blockIdx.x * 32, r0 = blockIdx.y * 32;
    int tx = threadIdx.x & 31, ty = threadIdx.x >> 5;
    const float* src = W + (size_t)e * R * C;
#pragma unroll
    for (int i = 0; i < 32; i += 8)
        tile[ty + i][tx] = src[(size_t)(r0 + ty + i) * C + c0 + tx];
    __syncthreads();
    __nv_bfloat16* dhi = Bhi + (size_t)e * R * C;
    __nv_bfloat16* dlo = Blo + (size_t)e * R * C;
#pragma unroll
    for (int i = 0; i < 32; i += 8) {
        int c = c0 + ty + i, r = r0 + tx;
        float v = tile[tx][ty + i];
        __nv_bfloat16 hi = __float2bfloat16(v);
        __nv_bfloat16 lo = __float2bfloat16(v - __bfloat162float(hi));
        dhi[(size_t)c * R + r] = hi;
        dlo[(size_t)c * R + r] = lo;
    }
}

// ---------------------------------------------------------------- GEMM 1+2 (mma)
// M=128 x N=64, K=DDIM, BK=32, bf16x3, plain LDG/STS single stage.
__global__ __launch_bounds__(256, 1) void gemm12_mma(const float* __restrict__ b1,
                                                     const float* __restrict__ b2)
{
    if (!flag_on()) return;
    __shared__ __align__(16) __nv_bfloat16 sAh[128][40];
    __shared__ __align__(16) __nv_bfloat16 sAl[128][40];
    __shared__ __align__(16) __nv_bfloat16 sB1h[64][40];
    __shared__ __align__(16) __nv_bfloat16 sB1l[64][40];
    __shared__ __align__(16) __nv_bfloat16 sB2h[64][40];
    __shared__ __align__(16) __nv_bfloat16 sB2l[64][40];

    int e = blockIdx.z;
    int cnt = g_cnt[e];
    int mbase = blockIdx.y * 128;
    if (mbase >= cnt) return;
    int off = g_off[e];
    int mrem = min(128, cnt - mbase);
    int n0 = blockIdx.x * 64;

    int tid = threadIdx.x, lane = tid & 31, wid = tid >> 5;
    int wm = wid >> 1, wn = wid & 1;
    int qr = lane >> 2, qc = (lane & 3) * 2;

    const uint4 *gAh[2], *gAl[2];
    uint4 *dAh[2], *dAl[2];
#pragma unroll
    for (int i = 0; i < 2; i++) {
        int idx = tid + i * 256;
        int row = idx >> 2, j = idx & 3;
        int r = min(row, mrem - 1);
        int tok = g_slot_token[off + mbase + r];
        gAh[i] = (const uint4*)(g_xhi + (size_t)tok * DDIM) + j;
        gAl[i] = (const uint4*)(g_xlo + (size_t)tok * DDIM) + j;
        dAh[i] = (uint4*)&sAh[row][j * 8];
        dAl[i] = (uint4*)&sAl[row][j * 8];
    }
    int brow = tid >> 2, bj = tid & 3;
    size_t brofs = ((size_t)e * HDIM + n0 + brow) * DDIM;
    const uint4* gB1h = (const uint4*)(g_w1hi + brofs) + bj;
    const uint4* gB1l = (const uint4*)(g_w1lo + brofs) + bj;
    const uint4* gB2h = (const uint4*)(g_w2hi + brofs) + bj;
    const uint4* gB2l = (const uint4*)(g_w2lo + brofs) + bj;
    uint4* dB1h = (uint4*)&sB1h[brow][bj * 8];
    uint4* dB1l = (uint4*)&sB1l[brow][bj * 8];
    uint4* dB2h = (uint4*)&sB2h[brow][bj * 8];
    uint4* dB2l = (uint4*)&sB2l[brow][bj * 8];

    float acch[2][4][4], accg[2][4][4];
#pragma unroll
    for (int a = 0; a < 2; a++)
#pragma unroll
        for (int b = 0; b < 4; b++)
#pragma unroll
            for (int c = 0; c < 4; c++) { acch[a][b][c] = 0.f; accg[a][b][c] = 0.f; }

    const int NIT = DDIM / 32;   // 24
    for (int it = 0; it < NIT; it++) {
        int kc = it * 4;                       // 16B chunks along k
#pragma unroll
        for (int i = 0; i < 2; i++) {
            *dAh[i] = gAh[i][kc];
            *dAl[i] = gAl[i][kc];
        }
        *dB1h = gB1h[kc];
        *dB1l = gB1l[kc];
        *dB2h = gB2h[kc];
        *dB2l = gB2l[kc];
        __syncthreads();

#pragma unroll
        for (int ks = 0; ks < 2; ks++) {
            int kb = ks * 16;
            uint32_t ah[2][4], al[2][4];
#pragma unroll
            for (int mt = 0; mt < 2; mt++) {
                int rb = wm * 32 + mt * 16 + qr;
                ah[mt][0] = *(const uint32_t*)&sAh[rb][kb + qc];
                ah[mt][1] = *(const uint32_t*)&sAh[rb + 8][kb + qc];
                ah[mt][2] = *(const uint32_t*)&sAh[rb][kb + qc + 8];
                ah[mt][3] = *(const uint32_t*)&sAh[rb + 8][kb + qc + 8];
                al[mt][0] = *(const uint32_t*)&sAl[rb][kb + qc];
                al[mt][1] = *(const uint32_t*)&sAl[rb + 8][kb + qc];
                al[mt][2] = *(const uint32_t*)&sAl[rb][kb + qc + 8];
                al[mt][3] = *(const uint32_t*)&sAl[rb + 8][kb + qc + 8];
            }
#pragma unroll
            for (int nt = 0; nt < 4; nt++) {
                int nb = wn * 32 + nt * 8 + qr;
                uint32_t bh0 = *(const uint32_t*)&sB1h[nb][kb + qc];
                uint32_t bh1 = *(const uint32_t*)&sB1h[nb][kb + qc + 8];
                uint32_t bl0 = *(const uint32_t*)&sB1l[nb][kb + qc];
                uint32_t bl1 = *(const uint32_t*)&sB1l[nb][kb + qc + 8];
#pragma unroll
                for (int mt = 0; mt < 2; mt++) {
                    mma_bf16(acch[mt][nt], ah[mt], bh0, bh1);
                    mma_bf16(acch[mt][nt], ah[mt], bl0, bl1);
                    mma_bf16(acch[mt][nt], al[mt], bh0, bh1);
                }
                bh0 = *(const uint32_t*)&sB2h[nb][kb + qc];
                bh1 = *(const uint32_t*)&sB2h[nb][kb + qc + 8];
                bl0 = *(const uint32_t*)&sB2l[nb][kb + qc];
                bl1 = *(const uint32_t*)&sB2l[nb][kb + qc + 8];
#pragma unroll
                for (int mt = 0; mt < 2; mt++) {
                    mma_bf16(accg[mt][nt], ah[mt], bh0, bh1);
                    mma_bf16(accg[mt][nt], ah[mt], bl0, bl1);
                    mma_bf16(accg[mt][nt], al[mt], bh0, bh1);
                }
            }
        }
        __syncthreads();
    }

    int tq2 = (lane & 3) * 2;
#pragma unroll
    for (int mt = 0; mt < 2; mt++)
#pragma unroll
    for (int p = 0; p < 2; p++) {
        int r = wm * 32 + mt * 16 + qr + p * 8;
        if (r < mrem) {
            size_t slot = (size_t)(off + mbase + r);
#pragma unroll
            for (int nt = 0; nt < 4; nt++) {
                int col = n0 + wn * 32 + nt * 8 + tq2;
                float h0 = acch[mt][nt][p * 2 + 0] + b1[e * HDIM + col];
                float h1 = acch[mt][nt][p * 2 + 1] + b1[e * HDIM + col + 1];
                float g0 = accg[mt][nt][p * 2 + 0] + b2[e * HDIM + col];
                float g1 = accg[mt][nt][p * 2 + 1] + b2[e * HDIM + col + 1];
                float a0 = h0 * (g0 / (1.f + expf(-g0)));
                float a1 = h1 * (g1 / (1.f + expf(-g1)));
                __nv_bfloat16 x0 = __float2bfloat16(a0);
                __nv_bfloat16 x1 = __float2bfloat16(a1);
                __nv_bfloat16 y0 = __float2bfloat16(a0 - __bfloat162float(x0));
                __nv_bfloat16 y1 = __float2bfloat16(a1 - __bfloat162float(x1));
                uint32_t ph = ((uint32_t)__bfloat16_as_ushort(x1) << 16) |
                              __bfloat16_as_ushort(x0);
                uint32_t pl = ((uint32_t)__bfloat16_as_ushort(y1) << 16) |
                              __bfloat16_as_ushort(y0);
                *(uint32_t*)(g_acthi + slot * HDIM + col) = ph;
                *(uint32_t*)(g_actlo + slot * HDIM + col) = pl;
            }
        }
    }
}

// verify gemm12: 64 sampled (slot,col), scalar fp32 recomputation
__global__ void verify12_kernel(const float* __restrict__ x,
                                const float* __restrict__ w1, const float* __restrict__ b1,
                                const float* __restrict__ w2, const float* __restrict__ b2)
{
    if (!flag_on()) return;
    int b = blockIdx.x, tid = threadIdx.x;
    int s = (b * 709 + 13) % NSLOT;
    int col = (b * 397 + 7) % HDIM;
    int e = 0;
#pragma unroll
    for (int i = 1; i < NE; i++) if (s >= g_off[i]) e = i;
    int tok = g_slot_token[s];
    float ph = 0.f, pg = 0.f;
    for (int d = tid; d < DDIM; d += 256) {
        float xv = x[(size_t)tok * DDIM + d];
        ph += xv * w1[((size_t)e * DDIM + d) * HDIM + col];
        pg += xv * w2[((size_t)e * DDIM + d) * HDIM + col];
    }
    __shared__ float sh[256], sg[256];
    sh[tid] = ph; sg[tid] = pg;
    __syncthreads();
    for (int st = 128; st > 0; st >>= 1) {
        if (tid < st) { sh[tid] += sh[tid + st]; sg[tid] += sg[tid + st]; }
        __syncthreads();
    }
    if (tid == 0) {
        float h = sh[0] + b1[e * HDIM + col];
        float g = sg[0] + b2[e * HDIM + col];
        float ref = h * (g / (1.f + expf(-g)));
        float got = __bfloat162float(g_acthi[(size_t)s * HDIM + col]) +
                    __bfloat162float(g_actlo[(size_t)s * HDIM + col]);
        if (fabsf(got - ref) > fmaxf(fabsf(ref) * 0.05f, 0.05f)) atomicExch(&g_ok, 0);
    }
}

// ---------------------------------------------------------------- GEMM 3 (mma)
__global__ __launch_bounds__(256, 1) void gemm3_mma(const float* __restrict__ bp)
{
    if (!flag_on()) return;
    __shared__ __align__(16) __nv_bfloat16 sAh[128][40];
    __shared__ __align__(16) __nv_bfloat16 sAl[128][40];
    __shared__ __align__(16) __nv_bfloat16 sBh[64][40];
    __shared__ __align__(16) __nv_bfloat16 sBl[64][40];

    int e = blockIdx.z;
    int cnt = g_cnt[e];
    int mbase = blockIdx.y * 128;
    if (mbase >= cnt) return;
    int off = g_off[e];
    int mrem = min(128, cnt - mbase);
    int n0 = blockIdx.x * 64;

    int tid = threadIdx.x, lane = tid & 31, wid = tid >> 5;
    int wm = wid >> 1, wn = wid & 1;
    int qr = lane >> 2, qc = (lane & 3) * 2;

    const uint4 *gAh[2], *gAl[2];
    uint4 *dAh[2], *dAl[2];
#pragma unroll
    for (int i = 0; i < 2; i++) {
        int idx = tid + i * 256;
        int row = idx >> 2, j = idx & 3;
        int r = min(row, mrem - 1);
        size_t arow = (size_t)(off + mbase + r) * HDIM;
        gAh[i] = (const uint4*)(g_acthi + arow) + j;
        gAl[i] = (const uint4*)(g_actlo + arow) + j;
        dAh[i] = (uint4*)&sAh[row][j * 8];
        dAl[i] = (uint4*)&sAl[row][j * 8];
    }
    int brow = tid >> 2, bj = tid & 3;
    size_t brofs = ((size_t)e * DDIM + n0 + brow) * HDIM;
    const uint4* gBh = (const uint4*)(g_wphi + brofs) + bj;
    const uint4* gBl = (const uint4*)(g_wplo + brofs) + bj;
    uint4* dBh = (uint4*)&sBh[brow][bj * 8];
    uint4* dBl = (uint4*)&sBl[brow][bj * 8];

    float acc[2][4][4];
#pragma unroll
    for (int a = 0; a < 2; a++)
#pragma unroll
        for (int b = 0; b < 4; b++)
#pragma unroll
            for (int c = 0; c < 4; c++) acc[a][b][c] = 0.f;

    const int NIT = HDIM / 32;   // 96
    for (int it = 0; it < NIT; it++) {
        int kc = it * 4;
#pragma unroll
        for (int i = 0; i < 2; i++) {
            *dAh[i] = gAh[i][kc];
            *dAl[i] = gAl[i][kc];
        }
        *dBh = gBh[kc];
        *dBl = gBl[kc];
        __syncthreads();

#pragma unroll
        for (int ks = 0; ks < 2; ks++) {
            int kb = ks * 16;
            uint32_t ah[2][4], al[2][4];
#pragma unroll
            for (int mt = 0; mt < 2; mt++) {
                int rb = wm * 32 + mt * 16 + qr;
                ah[mt][0] = *(const uint32_t*)&sAh[rb][kb + qc];
                ah[mt][1] = *(const uint32_t*)&sAh[rb + 8][kb + qc];
                ah[mt][2] = *(const uint32_t*)&sAh[rb][kb + qc + 8];
                ah[mt][3] = *(const uint32_t*)&sAh[rb + 8][kb + qc + 8];
                al[mt][0] = *(const uint32_t*)&sAl[rb][kb + qc];
                al[mt][1] = *(const uint32_t*)&sAl[rb + 8][kb + qc];
                al[mt][2] = *(const uint32_t*)&sAl[rb][kb + qc + 8];
                al[mt][3] = *(const uint32_t*)&sAl[rb + 8][kb + qc + 8];
            }
#pragma unroll
            for (int nt = 0; nt < 4; nt++) {
                int nb = wn * 32 + nt * 8 + qr;
                uint32_t bh0 = *(const uint32_t*)&sBh[nb][kb + qc];
                uint32_t bh1 = *(const uint32_t*)&sBh[nb][kb + qc + 8];
                uint32_t bl0 = *(const uint32_t*)&sBl[nb][kb + qc];
                uint32_t bl1 = *(const uint32_t*)&sBl[nb][kb + qc + 8];
#pragma unroll
                for (int mt = 0; mt < 2; mt++) {
                    mma_bf16(acc[mt][nt], ah[mt], bh0, bh1);
                    mma_bf16(acc[mt][nt], ah[mt], bl0, bl1);
                    mma_bf16(acc[mt][nt], al[mt], bh0, bh1);
                }
            }
        }
        __syncthreads();
    }

    int tq2 = (lane & 3) * 2;
#pragma unroll
    for (int mt = 0; mt < 2; mt++)
#pragma unroll
    for (int p = 0; p < 2; p++) {
        int r = wm * 32 + mt * 16 + qr + p * 8;
        if (r < mrem) {
            size_t slot = (size_t)(off + mbase + r);
#pragma unroll
            for (int nt = 0; nt < 4; nt++) {
                int col = n0 + wn * 32 + nt * 8 + tq2;
                float2 v;
                v.x = acc[mt][nt][p * 2 + 0] + bp[e * DDIM + col];
                v.y = acc[mt][nt][p * 2 + 1] + bp[e * DDIM + col + 1];
                *(float2*)(g_y + slot * DDIM + col) = v;
            }
        }
    }
}

// verify gemm3 against scalar dot of the (already verified) activations
__global__ void verify3_kernel(const float* __restrict__ wp, const float* __restrict__ bp)
{
    if (!flag_on()) return;
    int b = blockIdx.x, tid = threadIdx.x;
    int s = (b * 547 + 29) % NSLOT;
    int c = (b * 131 + 3) % DDIM;
    int e = 0;
#pragma unroll
    for (int i = 1; i < NE; i++) if (s >= g_off[i]) e = i;
    float p = 0.f;
    for (int hh = tid; hh < HDIM; hh += 256) {
        float av = __bfloat162float(g_acthi[(size_t)s * HDIM + hh]) +
                   __bfloat162float(g_actlo[(size_t)s * HDIM + hh]);
        p += av * wp[((size_t)e * HDIM + hh) * DDIM + c];
    }
    __shared__ float sh[256];
    sh[tid] = p;
    __syncthreads();
    for (int st = 128; st > 0; st >>= 1) {
        if (tid < st) sh[tid] += sh[tid + st];
        __syncthreads();
    }
    if (tid == 0) {
        float ref = sh[0] + bp[e * DDIM + c];
        float got = g_y[(size_t)s * DDIM + c];
        if (fabsf(got - ref) > fmaxf(fabsf(ref) * 0.05f, 0.05f)) atomicExch(&g_ok, 0);
    }
}

// ---------------------------------------------------------------- scalar fallback (R1)
__global__ __launch_bounds__(256, 2)
void sgemm_scalar(const float* __restrict__ X,
                  const float* __restrict__ W,
                  const float* __restrict__ bias,
                  int Kdim, int Ndim, int mode)
{
    if (flag_on()) return;
    int e = blockIdx.z;
    int cnt = g_cnt[e];
    int mbase = blockIdx.y * BM;
    if (mbase >= cnt) return;
    int off = g_off[e];
    int mrem = cnt - mbase;
    int n0 = blockIdx.x * BN;

    float* C = (mode == 0) ? g_h : (mode == 1) ? g_g : g_y;
    const float* A = (mode == 2) ? g_h : X;

    const float* arp[2];
#pragma unroll
    for (int i = 0; i < 2; i++) {
        int idx = threadIdx.x + i * 256;
        int ar = idx >> 2;
        int r = (ar < mrem) ? ar : 0;
        int slot = off + mbase + r;
        if (mode == 2) arp[i] = A + (size_t)slot * Kdim;
        else           arp[i] = A + (size_t)g_slot_token[slot] * Kdim;
    }
    const float* Wp = W + (size_t)e * Kdim * Ndim + n0;

    __shared__ float As[BK][BM];
    __shared__ float Bs[BK][BN];

    float accv[8][8];
#pragma unroll
    for (int mi = 0; mi < 8; mi++)
#pragma unroll
        for (int ni = 0; ni < 8; ni++) accv[mi][ni] = 0.f;

    int tx = threadIdx.x & 15;
    int ty = threadIdx.x >> 4;
    int mt = ty * 8;
    int nt = tx * 8;

    for (int k0 = 0; k0 < Kdim; k0 += BK) {
#pragma unroll
        for (int i = 0; i < 2; i++) {
            int idx = threadIdx.x + i * 256;
            int ar = idx >> 2, a4 = idx & 3;
            float4 v = *(const float4*)(arp[i] + k0 + a4 * 4);
            As[a4 * 4 + 0][ar] = v.x;
            As[a4 * 4 + 1][ar] = v.y;
            As[a4 * 4 + 2][ar] = v.z;
            As[a4 * 4 + 3][ar] = v.w;
        }
#pragma unroll
        for (int i = 0; i < 2; i++) {
            int idx = threadIdx.x + i * 256;
            int br = idx >> 5, b4 = idx & 31;
            *(float4*)&Bs[br][b4 * 4] =
                *(const float4*)(Wp + (size_t)(k0 + br) * Ndim + b4 * 4);
        }
        __syncthreads();
#pragma unroll
        for (int k = 0; k < BK; k++) {
            float a[8], bb[8];
            *(float4*)&a[0] = *(const float4*)&As[k][mt];
            *(float4*)&a[4] = *(const float4*)&As[k][mt + 4];
            *(float4*)&bb[0] = *(const float4*)&Bs[k][nt];
            *(float4*)&bb[4] = *(const float4*)&Bs[k][nt + 4];
#pragma unroll
            for (int mi = 0; mi < 8; mi++)
#pragma unroll
                for (int ni = 0; ni < 8; ni++)
                    accv[mi][ni] += a[mi] * bb[ni];
        }
        __syncthreads();
    }

    float bl[8];
    *(float4*)&bl[0] = *(const float4*)(bias + (size_t)e * Ndim + n0 + nt);
    *(float4*)&bl[4] = *(const float4*)(bias + (size_t)e * Ndim + n0 + nt + 4);

#pragma unroll
    for (int mi = 0; mi < 8; mi++) {
        int gm = mt + mi;
        if (gm < mrem) {
            size_t row = (size_t)(off + mbase + gm);
            float* cp = C + row * Ndim + n0 + nt;
            float4 v0 = make_float4(accv[mi][0] + bl[0], accv[mi][1] + bl[1],
                                    accv[mi][2] + bl[2], accv[mi][3] + bl[3]);
            float4 v1 = make_float4(accv[mi][4] + bl[4], accv[mi][5] + bl[5],
                                    accv[mi][6] + bl[6], accv[mi][7] + bl[7]);
            *(float4*)cp = v0;
            *(float4*)(cp + 4) = v1;
        }
    }
}

__global__ void act_kernel()
{
    if (flag_on()) return;
    size_t i = (size_t)blockIdx.x * blockDim.x + threadIdx.x;
    float4* hp = (float4*)g_h;
    const float4* gp = (const float4*)g_g;
    float4 g4 = gp[i];
    float4 h4 = hp[i];
    h4.x = h4.x * (g4.x / (1.f + expf(-g4.x)));
    h4.y = h4.y * (g4.y / (1.f + expf(-g4.y)));
    h4.z = h4.z * (g4.z / (1.f + expf(-g4.z)));
    h4.w = h4.w * (g4.w / (1.f + expf(-g4.w)));
    hp[i] = h4;
}

// ---------------------------------------------------------------- combine
__global__ void combine_kernel(float* __restrict__ out) {
    int f = blockIdx.x * blockDim.x + threadIdx.x;
    int t = f / (DDIM / 4);
    int j = f % (DDIM / 4);
    int s0 = g_tok_slot[t * 2 + 0];
    int s1 = g_tok_slot[t * 2 + 1];
    float g0 = g_tok_gate[t * 2 + 0];
    float g1 = g_tok_gate[t * 2 + 1];
    const float4* y = (const float4*)g_y;
    float4 a = y[(size_t)s0 * (DDIM / 4) + j];
    float4 b = y[(size_t)s1 * (DDIM / 4) + j];
    float4 o;
    o.x = g0 * a.x + g1 * b.x;
    o.y = g0 * a.y + g1 * b.y;
    o.z = g0 * a.z + g1 * b.z;
    o.w = g0 * a.w + g1 * b.w;
    ((float4*)out)[f] = o;
}

// ---------------------------------------------------------------- launch
extern "C" void kernel_launch(void* const* d_in, const int* in_sizes, int n_in,
                              void* d_out, int out_size)
{
    const float* x     = (const float*)d_in[0];
    const float* noise = (const float*)d_in[1];
    const float* gw    = (const float*)d_in[2];
    const float* nw    = (const float*)d_in[3];
    const float* w1    = (const float*)d_in[4];
    const float* b1    = (const float*)d_in[5];
    const float* w2    = (const float*)d_in[6];
    const float* b2    = (const float*)d_in[7];
    const float* wp    = (const float*)d_in[8];
    const float* bp    = (const float*)d_in[9];

    float* out = (float*)d_out;
    float* out_ids = nullptr;
    float* out_lb  = nullptr;
    if (out_size >= T_TOK * DDIM + NSLOT)     out_ids = out + (size_t)T_TOK * DDIM;
    if (out_size >= T_TOK * DDIM + NSLOT + 1) out_lb  = out + (size_t)T_TOK * DDIM + NSLOT;

    zero_stats<<<1, 32>>>();
    probe_kernel<<<1, 32>>>();
    gate_kernel<<<T_TOK, 128>>>(x, noise, gw, nw, out_ids);
    finalize_kernel<<<1, 1>>>(out_lb);
    scatter_kernel<<<(T_TOK + 255) / 256, 256>>>();

    // ---- mma path (self-gated) ----
    convert_x_kernel<<<T_TOK * DDIM / 4 / 256, 256>>>(x);
    transpose_convert<<<dim3(HDIM / 32, DDIM / 32, NE), 256>>>(w1, g_w1hi, g_w1lo, DDIM, HDIM);
    transpose_convert<<<dim3(HDIM / 32, DDIM / 32, NE), 256>>>(w2, g_w2hi, g_w2lo, DDIM, HDIM);
    transpose_convert<<<dim3(DDIM / 32, HDIM / 32, NE), 256>>>(wp, g_wphi, g_wplo, HDIM, DDIM);

    gemm12_mma<<<dim3(HDIM / 64, NSLOT / 128, NE), 256>>>(b1, b2);
    verify12_kernel<<<64, 256>>>(x, w1, b1, w2, b2);
    gemm3_mma<<<dim3(DDIM / 64, NSLOT / 128, NE), 256>>>(bp);
    verify3_kernel<<<64, 256>>>(wp, bp);

    // ---- scalar fallback (runs only if any check failed) ----
    dim3 gs1(HDIM / BN, T_TOK / BM, NE);
    sgemm_scalar<<<gs1, 256>>>(x, w1, b1, DDIM, HDIM, 0);
    sgemm_scalar<<<gs1, 256>>>(x, w2, b2, DDIM, HDIM, 1);
    act_kernel<<<(size_t)NSLOT * HDIM / 4 / 256, 256>>>();
    dim3 gs2(DDIM / BN, T_TOK / BM, NE);
    sgemm_scalar<<<gs2, 256>>>(nullptr, wp, bp, HDIM, DDIM, 2);

    combine_kernel<<<T_TOK * DDIM / 4 / 256, 256>>>(out);
}

// round 7
// speedup vs baseline: 1.0441x; 1.0441x over previous
#include <cuda_runtime.h>
#include <cuda_bf16.h>
#include <cstdint>
#include <math.h>

#define T_TOK 2048
#define NE 8
#define DDIM 768
#define HDIM 3072
#define NSLOT (T_TOK * 2)

#define BM 128
#define BN 128
#define BK 16

// ---------------------------------------------------------------- helpers
__device__ __forceinline__ uint32_t smem_u32(const void* p) {
    uint32_t a;
    asm("{ .reg .u64 t; cvta.to.shared.u64 t, %1; cvt.u32.u64 %0, t; }"
        : "=r"(a) : "l"(p));
    return a;
}
__device__ __forceinline__ void cpa16(uint32_t s, const void* g) {
    asm volatile("cp.async.cg.shared.global [%0], [%1], 16;"
                 :: "r"(s), "l"(g) : "memory");
}
#define CP_COMMIT() asm volatile("cp.async.commit_group;" ::: "memory")
#define CP_WAIT(n)  asm volatile("cp.async.wait_group %0;" :: "n"(n) : "memory")

__device__ __forceinline__ void mma_bf16(float* c, const uint32_t* a,
                                         uint32_t b0, uint32_t b1) {
    asm volatile("mma.sync.aligned.m16n8k16.row.col.f32.bf16.bf16.f32 "
        "{%0,%1,%2,%3}, {%4,%5,%6,%7}, {%8,%9}, {%0,%1,%2,%3};"
        : "+f"(c[0]), "+f"(c[1]), "+f"(c[2]), "+f"(c[3])
        : "r"(a[0]), "r"(a[1]), "r"(a[2]), "r"(a[3]), "r"(b0), "r"(b1));
}

// ---------------------------------------------------------------- scratch
__device__ int g_ok;
__device__ float g_h[(size_t)NSLOT * HDIM];
__device__ float g_g[(size_t)NSLOT * HDIM];
__device__ float g_y[(size_t)NSLOT * DDIM];
__device__ __align__(16) __nv_bfloat16 g_xhi[T_TOK * DDIM];
__device__ __align__(16) __nv_bfloat16 g_xlo[T_TOK * DDIM];
__device__ __align__(16) __nv_bfloat16 g_w1hi[(size_t)NE * HDIM * DDIM]; // [e][h][d]
__device__ __align__(16) __nv_bfloat16 g_w1lo[(size_t)NE * HDIM * DDIM];
__device__ __align__(16) __nv_bfloat16 g_w2hi[(size_t)NE * HDIM * DDIM];
__device__ __align__(16) __nv_bfloat16 g_w2lo[(size_t)NE * HDIM * DDIM];
__device__ __align__(16) __nv_bfloat16 g_wphi[(size_t)NE * DDIM * HDIM]; // [e][d][h]
__device__ __align__(16) __nv_bfloat16 g_wplo[(size_t)NE * DDIM * HDIM];
__device__ __align__(16) __nv_bfloat16 g_acthi[(size_t)NSLOT * HDIM];
__device__ __align__(16) __nv_bfloat16 g_actlo[(size_t)NSLOT * HDIM];
__device__ int   g_cnt[NE];
__device__ int   g_cnt2[NE];
__device__ int   g_off[NE];
__device__ float g_probs[NE];
__device__ int   g_slot_token[NSLOT];
__device__ int   g_tok_slot[NSLOT];
__device__ float g_tok_gate[NSLOT];
__device__ int   g_tok_exp[NSLOT];

__device__ __forceinline__ int flag_on() { return *(volatile int*)&g_ok; }

// ---------------------------------------------------------------- gate path
__global__ void zero_stats() {
    int i = threadIdx.x;
    if (i < NE) { g_cnt[i] = 0; g_probs[i] = 0.f; }
    if (i == 0) g_ok = 1;
}

__global__ void probe_kernel() {
    __shared__ __align__(16) __nv_bfloat16 sA[16][40];
    __shared__ __align__(16) __nv_bfloat16 sB[8][40];
    __shared__ int sbad;
    int lane = threadIdx.x;
    if (lane == 0) sbad = 0;
    for (int i = lane; i < 256; i += 32) {
        int m = i >> 4, k = i & 15;
        sA[m][k] = __float2bfloat16(0.03f * m - 0.07f * k + 0.11f);
    }
    for (int i = lane; i < 128; i += 32) {
        int n = i >> 4, k = i & 15;
        sB[n][k] = __float2bfloat16(0.05f * n + 0.02f * k - 0.3f);
    }
    __syncthreads();
    int qr = lane >> 2, qc = (lane & 3) * 2;
    uint32_t a[4], b0, b1;
    a[0] = *(const uint32_t*)&sA[qr][qc];
    a[1] = *(const uint32_t*)&sA[qr + 8][qc];
    a[2] = *(const uint32_t*)&sA[qr][qc + 8];
    a[3] = *(const uint32_t*)&sA[qr + 8][qc + 8];
    b0 = *(const uint32_t*)&sB[qr][qc];
    b1 = *(const uint32_t*)&sB[qr][qc + 8];
    float c[4] = {0.f, 0.f, 0.f, 0.f};
    mma_bf16(c, a, b0, b1);
#pragma unroll
    for (int i = 0; i < 4; i++) {
        int row = qr + (i >> 1) * 8;
        int col = (lane & 3) * 2 + (i & 1);
        float ref = 0.f;
        for (int k = 0; k < 16; k++) {
            float av = __bfloat162float(__float2bfloat16(0.03f * row - 0.07f * k + 0.11f));
            float bv = __bfloat162float(__float2bfloat16(0.05f * col + 0.02f * k - 0.3f));
            ref += av * bv;
        }
        if (fabsf(c[i] - ref) > 1e-2f) atomicExch(&sbad, 1);
    }
    __syncthreads();
    if (lane == 0 && sbad) g_ok = 0;
}

__global__ void gate_kernel(const float* __restrict__ x,
                            const float* __restrict__ noise,
                            const float* __restrict__ gw,
                            const float* __restrict__ nw,
                            float* __restrict__ out_ids)
{
    int t = blockIdx.x;
    int tid = threadIdx.x;
    const float* xr = x + (size_t)t * DDIM;

    float acc[NE];
#pragma unroll
    for (int e = 0; e < NE; e++) acc[e] = 0.f;
    for (int d = tid; d < DDIM; d += 128) {
        float xv = xr[d];
        const float* w = gw + d * NE;
#pragma unroll
        for (int e = 0; e < NE; e++) acc[e] += xv * w[e];
    }

    __shared__ float sm[NE][128];
#pragma unroll
    for (int e = 0; e < NE; e++) sm[e][tid] = acc[e];
    __syncthreads();
    for (int s = 64; s > 0; s >>= 1) {
        if (tid < s) {
#pragma unroll
            for (int e = 0; e < NE; e++) sm[e][tid] += sm[e][tid + s];
        }
        __syncthreads();
    }

    if (tid == 0) {
        float lg[NE], ns[NE];
#pragma unroll
        for (int e = 0; e < NE; e++) {
            lg[e] = sm[e][0];
            ns[e] = lg[e] + noise[t * NE + e] * nw[e];
        }
        int i0 = 0;
#pragma unroll
        for (int e = 1; e < NE; e++) if (ns[e] > ns[i0]) i0 = e;
        int i1 = (i0 == 0) ? 1 : 0;
#pragma unroll
        for (int e = 0; e < NE; e++) if (e != i0 && ns[e] > ns[i1]) i1 = e;

        float q  = expf(ns[i1] - ns[i0]);
        float p1 = q / (1.f + q);
        float p0 = 1.f - p1;

        g_tok_exp[t * 2 + 0] = i0;  g_tok_exp[t * 2 + 1] = i1;
        g_tok_gate[t * 2 + 0] = p0; g_tok_gate[t * 2 + 1] = p1;
        if (out_ids) {
            out_ids[t * 2 + 0] = (float)i0;
            out_ids[t * 2 + 1] = (float)i1;
        }
        atomicAdd(&g_cnt[i0], 1);
        atomicAdd(&g_cnt[i1], 1);

        float m = lg[0];
#pragma unroll
        for (int e = 1; e < NE; e++) m = fmaxf(m, lg[e]);
        float ex[NE], sum = 0.f;
#pragma unroll
        for (int e = 0; e < NE; e++) { ex[e] = expf(lg[e] - m); sum += ex[e]; }
        float inv = 1.f / sum;
#pragma unroll
        for (int e = 0; e < NE; e++) atomicAdd(&g_probs[e], ex[e] * inv);
    }
}

__global__ void finalize_kernel(float* __restrict__ out_lb) {
    if (threadIdx.x == 0 && blockIdx.x == 0) {
        int off = 0;
        for (int e = 0; e < NE; e++) { g_off[e] = off; off += g_cnt[e]; g_cnt2[e] = 0; }
        float accv = 0.f;
        for (int e = 0; e < NE; e++) {
            float d = g_probs[e] / (float)T_TOK - 1.0f / (float)NE;
            accv += d * d;
        }
        if (out_lb) out_lb[0] = accv / (float)NE * 0.01f;
    }
}

__global__ void scatter_kernel() {
    int t = blockIdx.x * blockDim.x + threadIdx.x;
    if (t >= T_TOK) return;
#pragma unroll
    for (int k2 = 0; k2 < 2; k2++) {
        int e = g_tok_exp[t * 2 + k2];
        int pos = atomicAdd(&g_cnt2[e], 1);
        int slot = g_off[e] + pos;
        g_slot_token[slot] = t;
        g_tok_slot[t * 2 + k2] = slot;
    }
}

// ---------------------------------------------------------------- converts (gated)
__global__ void convert_x_kernel(const float* __restrict__ x) {
    if (!flag_on()) return;
    size_t i = (size_t)blockIdx.x * blockDim.x + threadIdx.x;
    float4 v = ((const float4*)x)[i];
    float vv[4] = { v.x, v.y, v.z, v.w };
    __nv_bfloat16 hb[4], lb[4];
#pragma unroll
    for (int j = 0; j < 4; j++) {
        hb[j] = __float2bfloat16(vv[j]);
        lb[j] = __float2bfloat16(vv[j] - __bfloat162float(hb[j]));
    }
    uint64_t hv, lv;
    memcpy(&hv, hb, 8); memcpy(&lv, lb, 8);
    *(uint64_t*)(g_xhi + i * 4) = hv;
    *(uint64_t*)(g_xlo + i * 4) = lv;
}

__global__ void transpose_convert(const float* __restrict__ W,
                                  __nv_bfloat16* __restrict__ Bhi,
                                  __nv_bfloat16* __restrict__ Blo,
                                  int R, int C)
{
    if (!flag_on()) return;
    __shared__ float tile[32][33];
    int e = blockIdx.z;
    int c0 = blockIdx.x * 32, r0 = blockIdx.y * 32;
    int tx = threadIdx.x & 31, ty = threadIdx.x >> 5;
    const float* src = W + (size_t)e * R * C;
#pragma unroll
    for (int i = 0; i < 32; i += 8)
        tile[ty + i][tx] = src[(size_t)(r0 + ty + i) * C + c0 + tx];
    __syncthreads();
    __nv_bfloat16* dhi = Bhi + (size_t)e * R * C;
    __nv_bfloat16* dlo = Blo + (size_t)e * R * C;
#pragma unroll
    for (int i = 0; i < 32; i += 8) {
        int c = c0 + ty + i, r = r0 + tx;
        float v = tile[tx][ty + i];
        __nv_bfloat16 hi = __float2bfloat16(v);
        __nv_bfloat16 lo = __float2bfloat16(v - __bfloat162float(hi));
        dhi[(size_t)c * R + r] = hi;
        dlo[(size_t)c * R + r] = lo;
    }
}

// ---------------------------------------------------------------- GEMM 1+2 (mma, pipelined)
// M=128 x N=64, K=DDIM, BK=16, bf16x3, 2-stage cp.async.
__global__ __launch_bounds__(256, 1) void gemm12_mma(const float* __restrict__ b1,
                                                     const float* __restrict__ b2)
{
    if (!flag_on()) return;
    __shared__ __align__(128) __nv_bfloat16 sA[2][2][128][16];  // [stage][hi/lo] 16 KB
    __shared__ __align__(128) __nv_bfloat16 sB[2][4][64][16];   // [stage][w1h,w1l,w2h,w2l] 16 KB

    int e = blockIdx.z;
    int cnt = g_cnt[e];
    int mbase = blockIdx.y * 128;
    if (mbase >= cnt) return;
    int off = g_off[e];
    int mrem = min(128, cnt - mbase);
    int n0 = blockIdx.x * 64;

    int tid = threadIdx.x, lane = tid & 31, wid = tid >> 5;
    int wm = wid >> 1, wn = wid & 1;
    int qr = lane >> 2, qc = (lane & 3) * 2;

    // A loader: one 16B chunk for hi + one for lo per thread
    int arow = tid >> 1, aj = tid & 1;
    int ar = min(arow, mrem - 1);
    int tok = g_slot_token[off + mbase + ar];
    const __nv_bfloat16* gAh = g_xhi + (size_t)tok * DDIM + aj * 8;
    const __nv_bfloat16* gAl = g_xlo + (size_t)tok * DDIM + aj * 8;
    uint32_t dAh[2], dAl[2];
    dAh[0] = smem_u32(&sA[0][0][arow][aj * 8]);
    dAh[1] = smem_u32(&sA[1][0][arow][aj * 8]);
    dAl[0] = smem_u32(&sA[0][1][arow][aj * 8]);
    dAl[1] = smem_u32(&sA[1][1][arow][aj * 8]);

    // B loader: two 16B chunks per thread across the 4 weight buffers
    const __nv_bfloat16* gB[2];
    uint32_t dB[2][2];
#pragma unroll
    for (int i = 0; i < 2; i++) {
        int idx = tid + i * 256;
        int buf = idx >> 7, row = (idx >> 1) & 63, j = idx & 1;
        const __nv_bfloat16* src =
            (buf == 0) ? g_w1hi : (buf == 1) ? g_w1lo : (buf == 2) ? g_w2hi : g_w2lo;
        gB[i] = src + ((size_t)e * HDIM + n0 + row) * DDIM + j * 8;
        dB[i][0] = smem_u32(&sB[0][buf][row][j * 8]);
        dB[i][1] = smem_u32(&sB[1][buf][row][j * 8]);
    }

    float acch[2][4][4], accg[2][4][4];
#pragma unroll
    for (int a = 0; a < 2; a++)
#pragma unroll
        for (int b = 0; b < 4; b++)
#pragma unroll
            for (int c = 0; c < 4; c++) { acch[a][b][c] = 0.f; accg[a][b][c] = 0.f; }

    const int NIT = DDIM / BK;   // 48
    // prologue: stage 0
    cpa16(dAh[0], gAh); cpa16(dAl[0], gAl);
    cpa16(dB[0][0], gB[0]); cpa16(dB[1][0], gB[1]);
    CP_COMMIT();

    for (int it = 0; it < NIT; it++) {
        if (it + 1 < NIT) {
            int st = (it + 1) & 1, k0 = (it + 1) * BK;
            cpa16(dAh[st], gAh + k0); cpa16(dAl[st], gAl + k0);
            cpa16(dB[0][st], gB[0] + k0); cpa16(dB[1][st], gB[1] + k0);
            CP_COMMIT();
            CP_WAIT(1);
        } else {
            CP_WAIT(0);
        }
        __syncthreads();
        int st = it & 1;

        uint32_t ah[2][4], al[2][4];
#pragma unroll
        for (int mt = 0; mt < 2; mt++) {
            int rb = wm * 32 + mt * 16 + qr;
            ah[mt][0] = *(const uint32_t*)&sA[st][0][rb][qc];
            ah[mt][1] = *(const uint32_t*)&sA[st][0][rb + 8][qc];
            ah[mt][2] = *(const uint32_t*)&sA[st][0][rb][qc + 8];
            ah[mt][3] = *(const uint32_t*)&sA[st][0][rb + 8][qc + 8];
            al[mt][0] = *(const uint32_t*)&sA[st][1][rb][qc];
            al[mt][1] = *(const uint32_t*)&sA[st][1][rb + 8][qc];
            al[mt][2] = *(const uint32_t*)&sA[st][1][rb][qc + 8];
            al[mt][3] = *(const uint32_t*)&sA[st][1][rb + 8][qc + 8];
        }
#pragma unroll
        for (int nt = 0; nt < 4; nt++) {
            int nb = wn * 32 + nt * 8 + qr;
            uint32_t bh0 = *(const uint32_t*)&sB[st][0][nb][qc];
            uint32_t bh1 = *(const uint32_t*)&sB[st][0][nb][qc + 8];
            uint32_t bl0 = *(const uint32_t*)&sB[st][1][nb][qc];
            uint32_t bl1 = *(const uint32_t*)&sB[st][1][nb][qc + 8];
#pragma unroll
            for (int mt = 0; mt < 2; mt++) {
                mma_bf16(acch[mt][nt], ah[mt], bh0, bh1);
                mma_bf16(acch[mt][nt], ah[mt], bl0, bl1);
                mma_bf16(acch[mt][nt], al[mt], bh0, bh1);
            }
            bh0 = *(const uint32_t*)&sB[st][2][nb][qc];
            bh1 = *(const uint32_t*)&sB[st][2][nb][qc + 8];
            bl0 = *(const uint32_t*)&sB[st][3][nb][qc];
            bl1 = *(const uint32_t*)&sB[st][3][nb][qc + 8];
#pragma unroll
            for (int mt = 0; mt < 2; mt++) {
                mma_bf16(accg[mt][nt], ah[mt], bh0, bh1);
                mma_bf16(accg[mt][nt], ah[mt], bl0, bl1);
                mma_bf16(accg[mt][nt], al[mt], bh0, bh1);
            }
        }
        __syncthreads();
    }

    int tq2 = (lane & 3) * 2;
#pragma unroll
    for (int mt = 0; mt < 2; mt++)
#pragma unroll
    for (int p = 0; p < 2; p++) {
        int r = wm * 32 + mt * 16 + qr + p * 8;
        if (r < mrem) {
            size_t slot = (size_t)(off + mbase + r);
#pragma unroll
            for (int nt = 0; nt < 4; nt++) {
                int col = n0 + wn * 32 + nt * 8 + tq2;
                float h0 = acch[mt][nt][p * 2 + 0] + b1[e * HDIM + col];
                float h1 = acch[mt][nt][p * 2 + 1] + b1[e * HDIM + col + 1];
                float g0 = accg[mt][nt][p * 2 + 0] + b2[e * HDIM + col];
                float g1 = accg[mt][nt][p * 2 + 1] + b2[e * HDIM + col + 1];
                float a0 = h0 * (g0 / (1.f + expf(-g0)));
                float a1 = h1 * (g1 / (1.f + expf(-g1)));
                __nv_bfloat16 x0 = __float2bfloat16(a0);
                __nv_bfloat16 x1 = __float2bfloat16(a1);
                __nv_bfloat16 y0 = __float2bfloat16(a0 - __bfloat162float(x0));
                __nv_bfloat16 y1 = __float2bfloat16(a1 - __bfloat162float(x1));
                uint32_t ph = ((uint32_t)__bfloat16_as_ushort(x1) << 16) |
                              __bfloat16_as_ushort(x0);
                uint32_t pl = ((uint32_t)__bfloat16_as_ushort(y1) << 16) |
                              __bfloat16_as_ushort(y0);
                *(uint32_t*)(g_acthi + slot * HDIM + col) = ph;
                *(uint32_t*)(g_actlo + slot * HDIM + col) = pl;
            }
        }
    }
}

__global__ void verify12_kernel(const float* __restrict__ x,
                                const float* __restrict__ w1, const float* __restrict__ b1,
                                const float* __restrict__ w2, const float* __restrict__ b2)
{
    if (!flag_on()) return;
    int b = blockIdx.x, tid = threadIdx.x;
    int s = (b * 709 + 13) % NSLOT;
    int col = (b * 397 + 7) % HDIM;
    int e = 0;
#pragma unroll
    for (int i = 1; i < NE; i++) if (s >= g_off[i]) e = i;
    int tok = g_slot_token[s];
    float ph = 0.f, pg = 0.f;
    for (int d = tid; d < DDIM; d += 256) {
        float xv = x[(size_t)tok * DDIM + d];
        ph += xv * w1[((size_t)e * DDIM + d) * HDIM + col];
        pg += xv * w2[((size_t)e * DDIM + d) * HDIM + col];
    }
    __shared__ float sh[256], sg[256];
    sh[tid] = ph; sg[tid] = pg;
    __syncthreads();
    for (int st = 128; st > 0; st >>= 1) {
        if (tid < st) { sh[tid] += sh[tid + st]; sg[tid] += sg[tid + st]; }
        __syncthreads();
    }
    if (tid == 0) {
        float h = sh[0] + b1[e * HDIM + col];
        float g = sg[0] + b2[e * HDIM + col];
        float ref = h * (g / (1.f + expf(-g)));
        float got = __bfloat162float(g_acthi[(size_t)s * HDIM + col]) +
                    __bfloat162float(g_actlo[(size_t)s * HDIM + col]);
        if (fabsf(got - ref) > fmaxf(fabsf(ref) * 0.05f, 0.05f)) atomicExch(&g_ok, 0);
    }
}

// ---------------------------------------------------------------- GEMM 3 (mma, pipelined)
__global__ __launch_bounds__(256, 1) void gemm3_mma(const float* __restrict__ bp)
{
    if (!flag_on()) return;
    __shared__ __align__(128) __nv_bfloat16 sA[2][2][128][16];  // 16 KB
    __shared__ __align__(128) __nv_bfloat16 sB[2][2][64][16];   // 8 KB

    int e = blockIdx.z;
    int cnt = g_cnt[e];
    int mbase = blockIdx.y * 128;
    if (mbase >= cnt) return;
    int off = g_off[e];
    int mrem = min(128, cnt - mbase);
    int n0 = blockIdx.x * 64;

    int tid = threadIdx.x, lane = tid & 31, wid = tid >> 5;
    int wm = wid >> 1, wn = wid & 1;
    int qr = lane >> 2, qc = (lane & 3) * 2;

    int arow = tid >> 1, aj = tid & 1;
    int ar = min(arow, mrem - 1);
    size_t arbase = (size_t)(off + mbase + ar) * HDIM + aj * 8;
    const __nv_bfloat16* gAh = g_acthi + arbase;
    const __nv_bfloat16* gAl = g_actlo + arbase;
    uint32_t dAh[2], dAl[2];
    dAh[0] = smem_u32(&sA[0][0][arow][aj * 8]);
    dAh[1] = smem_u32(&sA[1][0][arow][aj * 8]);
    dAl[0] = smem_u32(&sA[0][1][arow][aj * 8]);
    dAl[1] = smem_u32(&sA[1][1][arow][aj * 8]);

    // B: 2 bufs x 64 rows x 2 chunks = 256 -> one chunk per thread
    int bbuf = tid >> 7, brow = (tid >> 1) & 63, bj = tid & 1;
    const __nv_bfloat16* gB =
        ((bbuf == 0) ? g_wphi : g_wplo) + ((size_t)e * DDIM + n0 + brow) * HDIM + bj * 8;
    uint32_t dB[2];
    dB[0] = smem_u32(&sB[0][bbuf][brow][bj * 8]);
    dB[1] = smem_u32(&sB[1][bbuf][brow][bj * 8]);

    float acc[2][4][4];
#pragma unroll
    for (int a = 0; a < 2; a++)
#pragma unroll
        for (int b = 0; b < 4; b++)
#pragma unroll
            for (int c = 0; c < 4; c++) acc[a][b][c] = 0.f;

    const int NIT = HDIM / BK;   // 192
    cpa16(dAh[0], gAh); cpa16(dAl[0], gAl); cpa16(dB[0], gB);
    CP_COMMIT();

    for (int it = 0; it < NIT; it++) {
        if (it + 1 < NIT) {
            int st = (it + 1) & 1, k0 = (it + 1) * BK;
            cpa16(dAh[st], gAh + k0); cpa16(dAl[st], gAl + k0); cpa16(dB[st], gB + k0);
            CP_COMMIT();
            CP_WAIT(1);
        } else {
            CP_WAIT(0);
        }
        __syncthreads();
        int st = it & 1;

        uint32_t ah[2][4], al[2][4];
#pragma unroll
        for (int mt = 0; mt < 2; mt++) {
            int rb = wm * 32 + mt * 16 + qr;
            ah[mt][0] = *(const uint32_t*)&sA[st][0][rb][qc];
            ah[mt][1] = *(const uint32_t*)&sA[st][0][rb + 8][qc];
            ah[mt][2] = *(const uint32_t*)&sA[st][0][rb][qc + 8];
            ah[mt][3] = *(const uint32_t*)&sA[st][0][rb + 8][qc + 8];
            al[mt][0] = *(const uint32_t*)&sA[st][1][rb][qc];
            al[mt][1] = *(const uint32_t*)&sA[st][1][rb + 8][qc];
            al[mt][2] = *(const uint32_t*)&sA[st][1][rb][qc + 8];
            al[mt][3] = *(const uint32_t*)&sA[st][1][rb + 8][qc + 8];
        }
#pragma unroll
        for (int nt = 0; nt < 4; nt++) {
            int nb = wn * 32 + nt * 8 + qr;
            uint32_t bh0 = *(const uint32_t*)&sB[st][0][nb][qc];
            uint32_t bh1 = *(const uint32_t*)&sB[st][0][nb][qc + 8];
            uint32_t bl0 = *(const uint32_t*)&sB[st][1][nb][qc];
            uint32_t bl1 = *(const uint32_t*)&sB[st][1][nb][qc + 8];
#pragma unroll
            for (int mt = 0; mt < 2; mt++) {
                mma_bf16(acc[mt][nt], ah[mt], bh0, bh1);
                mma_bf16(acc[mt][nt], ah[mt], bl0, bl1);
                mma_bf16(acc[mt][nt], al[mt], bh0, bh1);
            }
        }
        __syncthreads();
    }

    int tq2 = (lane & 3) * 2;
#pragma unroll
    for (int mt = 0; mt < 2; mt++)
#pragma unroll
    for (int p = 0; p < 2; p++) {
        int r = wm * 32 + mt * 16 + qr + p * 8;
        if (r < mrem) {
            size_t slot = (size_t)(off + mbase + r);
#pragma unroll
            for (int nt = 0; nt < 4; nt++) {
                int col = n0 + wn * 32 + nt * 8 + tq2;
                float2 v;
                v.x = acc[mt][nt][p * 2 + 0] + bp[e * DDIM + col];
                v.y = acc[mt][nt][p * 2 + 1] + bp[e * DDIM + col + 1];
                *(float2*)(g_y + slot * DDIM + col) = v;
            }
        }
    }
}

__global__ void verify3_kernel(const float* __restrict__ wp, const float* __restrict__ bp)
{
    if (!flag_on()) return;
    int b = blockIdx.x, tid = threadIdx.x;
    int s = (b * 547 + 29) % NSLOT;
    int c = (b * 131 + 3) % DDIM;
    int e = 0;
#pragma unroll
    for (int i = 1; i < NE; i++) if (s >= g_off[i]) e = i;
    float p = 0.f;
    for (int hh = tid; hh < HDIM; hh += 256) {
        float av = __bfloat162float(g_acthi[(size_t)s * HDIM + hh]) +
                   __bfloat162float(g_actlo[(size_t)s * HDIM + hh]);
        p += av * wp[((size_t)e * HDIM + hh) * DDIM + c];
    }
    __shared__ float sh[256];
    sh[tid] = p;
    __syncthreads();
    for (int st = 128; st > 0; st >>= 1) {
        if (tid < st) sh[tid] += sh[tid + st];
        __syncthreads();
    }
    if (tid == 0) {
        float ref = sh[0] + bp[e * DDIM + c];
        float got = g_y[(size_t)s * DDIM + c];
        if (fabsf(got - ref) > fmaxf(fabsf(ref) * 0.05f, 0.05f)) atomicExch(&g_ok, 0);
    }
}

// ---------------------------------------------------------------- scalar fallback
__global__ __launch_bounds__(256, 2)
void sgemm_scalar(const float* __restrict__ X,
                  const float* __restrict__ W,
                  const float* __restrict__ bias,
                  int Kdim, int Ndim, int mode)
{
    if (flag_on()) return;
    int e = blockIdx.z;
    int cnt = g_cnt[e];
    int mbase = blockIdx.y * BM;
    if (mbase >= cnt) return;
    int off = g_off[e];
    int mrem = cnt - mbase;
    int n0 = blockIdx.x * BN;

    float* C = (mode == 0) ? g_h : (mode == 1) ? g_g : g_y;
    const float* A = (mode == 2) ? g_h : X;

    const float* arp[2];
#pragma unroll
    for (int i = 0; i < 2; i++) {
        int idx = threadIdx.x + i * 256;
        int ar = idx >> 2;
        int r = (ar < mrem) ? ar : 0;
        int slot = off + mbase + r;
        if (mode == 2) arp[i] = A + (size_t)slot * Kdim;
        else           arp[i] = A + (size_t)g_slot_token[slot] * Kdim;
    }
    const float* Wp = W + (size_t)e * Kdim * Ndim + n0;

    __shared__ float As[BK][BM];
    __shared__ float Bs[BK][BN];

    float accv[8][8];
#pragma unroll
    for (int mi = 0; mi < 8; mi++)
#pragma unroll
        for (int ni = 0; ni < 8; ni++) accv[mi][ni] = 0.f;

    int tx = threadIdx.x & 15;
    int ty = threadIdx.x >> 4;
    int mt = ty * 8;
    int nt = tx * 8;

    for (int k0 = 0; k0 < Kdim; k0 += BK) {
#pragma unroll
        for (int i = 0; i < 2; i++) {
            int idx = threadIdx.x + i * 256;
            int ar = idx >> 2, a4 = idx & 3;
            float4 v = *(const float4*)(arp[i] + k0 + a4 * 4);
            As[a4 * 4 + 0][ar] = v.x;
            As[a4 * 4 + 1][ar] = v.y;
            As[a4 * 4 + 2][ar] = v.z;
            As[a4 * 4 + 3][ar] = v.w;
        }
#pragma unroll
        for (int i = 0; i < 2; i++) {
            int idx = threadIdx.x + i * 256;
            int br = idx >> 5, b4 = idx & 31;
            *(float4*)&Bs[br][b4 * 4] =
                *(const float4*)(Wp + (size_t)(k0 + br) * Ndim + b4 * 4);
        }
        __syncthreads();
#pragma unroll
        for (int k = 0; k < BK; k++) {
            float a[8], bb[8];
            *(float4*)&a[0] = *(const float4*)&As[k][mt];
            *(float4*)&a[4] = *(const float4*)&As[k][mt + 4];
            *(float4*)&bb[0] = *(const float4*)&Bs[k][nt];
            *(float4*)&bb[4] = *(const float4*)&Bs[k][nt + 4];
#pragma unroll
            for (int mi = 0; mi < 8; mi++)
#pragma unroll
                for (int ni = 0; ni < 8; ni++)
                    accv[mi][ni] += a[mi] * bb[ni];
        }
        __syncthreads();
    }

    float bl[8];
    *(float4*)&bl[0] = *(const float4*)(bias + (size_t)e * Ndim + n0 + nt);
    *(float4*)&bl[4] = *(const float4*)(bias + (size_t)e * Ndim + n0 + nt + 4);

#pragma unroll
    for (int mi = 0; mi < 8; mi++) {
        int gm = mt + mi;
        if (gm < mrem) {
            size_t row = (size_t)(off + mbase + gm);
            float* cp = C + row * Ndim + n0 + nt;
            float4 v0 = make_float4(accv[mi][0] + bl[0], accv[mi][1] + bl[1],
                                    accv[mi][2] + bl[2], accv[mi][3] + bl[3]);
            float4 v1 = make_float4(accv[mi][4] + bl[4], accv[mi][5] + bl[5],
                                    accv[mi][6] + bl[6], accv[mi][7] + bl[7]);
            *(float4*)cp = v0;
            *(float4*)(cp + 4) = v1;
        }
    }
}

__global__ void act_kernel()
{
    if (flag_on()) return;
    size_t i = (size_t)blockIdx.x * blockDim.x + threadIdx.x;
    float4* hp = (float4*)g_h;
    const float4* gp = (const float4*)g_g;
    float4 g4 = gp[i];
    float4 h4 = hp[i];
    h4.x = h4.x * (g4.x / (1.f + expf(-g4.x)));
    h4.y = h4.y * (g4.y / (1.f + expf(-g4.y)));
    h4.z = h4.z * (g4.z / (1.f + expf(-g4.z)));
    h4.w = h4.w * (g4.w / (1.f + expf(-g4.w)));
    hp[i] = h4;
}

// ---------------------------------------------------------------- combine
__global__ void combine_kernel(float* __restrict__ out) {
    int f = blockIdx.x * blockDim.x + threadIdx.x;
    int t = f / (DDIM / 4);
    int j = f % (DDIM / 4);
    int s0 = g_tok_slot[t * 2 + 0];
    int s1 = g_tok_slot[t * 2 + 1];
    float g0 = g_tok_gate[t * 2 + 0];
    float g1 = g_tok_gate[t * 2 + 1];
    const float4* y = (const float4*)g_y;
    float4 a = y[(size_t)s0 * (DDIM / 4) + j];
    float4 b = y[(size_t)s1 * (DDIM / 4) + j];
    float4 o;
    o.x = g0 * a.x + g1 * b.x;
    o.y = g0 * a.y + g1 * b.y;
    o.z = g0 * a.z + g1 * b.z;
    o.w = g0 * a.w + g1 * b.w;
    ((float4*)out)[f] = o;
}

// ---------------------------------------------------------------- launch
extern "C" void kernel_launch(void* const* d_in, const int* in_sizes, int n_in,
                              void* d_out, int out_size)
{
    const float* x     = (const float*)d_in[0];
    const float* noise = (const float*)d_in[1];
    const float* gw    = (const float*)d_in[2];
    const float* nw    = (const float*)d_in[3];
    const float* w1    = (const float*)d_in[4];
    const float* b1    = (const float*)d_in[5];
    const float* w2    = (const float*)d_in[6];
    const float* b2    = (const float*)d_in[7];
    const float* wp    = (const float*)d_in[8];
    const float* bp    = (const float*)d_in[9];

    float* out = (float*)d_out;
    float* out_ids = nullptr;
    float* out_lb  = nullptr;
    if (out_size >= T_TOK * DDIM + NSLOT)     out_ids = out + (size_t)T_TOK * DDIM;
    if (out_size >= T_TOK * DDIM + NSLOT + 1) out_lb  = out + (size_t)T_TOK * DDIM + NSLOT;

    zero_stats<<<1, 32>>>();
    probe_kernel<<<1, 32>>>();
    gate_kernel<<<T_TOK, 128>>>(x, noise, gw, nw, out_ids);
    finalize_kernel<<<1, 1>>>(out_lb);
    scatter_kernel<<<(T_TOK + 255) / 256, 256>>>();

    // ---- mma path (self-gated) ----
    convert_x_kernel<<<T_TOK * DDIM / 4 / 256, 256>>>(x);
    transpose_convert<<<dim3(HDIM / 32, DDIM / 32, NE), 256>>>(w1, g_w1hi, g_w1lo, DDIM, HDIM);
    transpose_convert<<<dim3(HDIM / 32, DDIM / 32, NE), 256>>>(w2, g_w2hi, g_w2lo, DDIM, HDIM);
    transpose_convert<<<dim3(DDIM / 32, HDIM / 32, NE), 256>>>(wp, g_wphi, g_wplo, HDIM, DDIM);

    gemm12_mma<<<dim3(HDIM / 64, NSLOT / 128, NE), 256>>>(b1, b2);
    verify12_kernel<<<64, 256>>>(x, w1, b1, w2, b2);
    gemm3_mma<<<dim3(DDIM / 64, NSLOT / 128, NE), 256>>>(bp);
    verify3_kernel<<<64, 256>>>(wp, bp);

    // ---- scalar fallback (runs only if any check failed) ----
    dim3 gs1(HDIM / BN, T_TOK / BM, NE);
    sgemm_scalar<<<gs1, 256>>>(x, w1, b1, DDIM, HDIM, 0);
    sgemm_scalar<<<gs1, 256>>>(x, w2, b2, DDIM, HDIM, 1);
    act_kernel<<<(size_t)NSLOT * HDIM / 4 / 256, 256>>>();
    dim3 gs2(DDIM / BN, T_TOK / BM, NE);
    sgemm_scalar<<<gs2, 256>>>(nullptr, wp, bp, HDIM, DDIM, 2);

    combine_kernel<<<T_TOK * DDIM / 4 / 256, 256>>>(out);
}